// round 5
// baseline (speedup 1.0000x reference)
#include <cuda_runtime.h>
#include <math.h>
#include <stdint.h>

#define BATCH   128
#define TT      504
#define TF      502      // tokens after features[:,2:]
#define TC      500      // cond frames
#define NSTEP   2000
#define NT      512      // threads in scan CTA
#define BPC     4        // batch elems per CTA
#define NCTA    (BATCH / BPC)

// ---------------- transposed-weight offsets (floats) ----------------
#define OFF_FWC    0          // (192,328)
#define OFF_FWCG   62976      // (192,192)
#define OFF_G1IH   99840      // (480,272)
#define OFF_G1HH   230400     // (480,160)
#define OFF_GLU1   307200     // (160,160)
#define OFF_G2IH   332800     // (384,240)
#define OFF_G2HH   424960     // (384,128)
#define OFF_GLU2   474112     // (128,128)
#define OFF_G3IH   490496     // (384,208)
#define OFF_G3HH   570368     // (384,128)
#define OFF_GLU3   619520     // (128,128)
#define OFF_SKIP   635904     // (128,688)
#define OFF_SKIPG  723968     // (128,128)
#define OFF_SIG    740352     // (40,128)
#define OFF_GOUT   745472     // (4,192)
#define WT_TOTAL   746240

// ---------------- device scratch (no allocations allowed) ----------------
__device__ float g_x[BATCH * TF * 64];        // fd1 output
__device__ float g_cond[BATCH * TC * 320];    // fd2 output
__device__ float g_gain[NSTEP * BATCH];       // precomputed gains
__device__ float g_wt[WT_TOTAL];              // transposed weights [in][out]

__device__ __forceinline__ float sigf(float x) { return 1.0f / (1.0f + expf(-x)); }

// ---------------- f32x2 packed-fma helpers (batch-pair SIMD) ----------------
typedef unsigned long long u64;
__device__ __forceinline__ u64 pk2(float lo, float hi) {
    u64 r; asm("mov.b64 %0, {%1, %2};" : "=l"(r) : "f"(lo), "f"(hi)); return r;
}
__device__ __forceinline__ u64 dup2(float v) {
    u64 r; asm("mov.b64 %0, {%1, %1};" : "=l"(r) : "f"(v)); return r;
}
__device__ __forceinline__ void fma2(u64& d, u64 a, u64 b) {
    asm("fma.rn.f32x2 %0, %1, %2, %3;" : "=l"(d) : "l"(a), "l"(b), "l"(d));
}
__device__ __forceinline__ float2 upk(u64 v) {
    float2 r; asm("mov.b64 {%0, %1}, %2;" : "=f"(r.x), "=f"(r.y) : "l"(v)); return r;
}

__device__ __forceinline__ float4 sig4v(float4 a) {
    return make_float4(sigf(a.x), sigf(a.y), sigf(a.z), sigf(a.w));
}
__device__ __forceinline__ float4 tanh4v(float4 a) {
    return make_float4(tanhf(a.x), tanhf(a.y), tanhf(a.z), tanhf(a.w));
}

// ---------------- fused weight transpose: Wt[k*out+o] = W[o*in+k] ----------------
struct WP { const float* p[15]; };
__constant__ int T_OFF[15] = {OFF_FWC, OFF_FWCG, OFF_G1IH, OFF_G1HH, OFF_GLU1,
                              OFF_G2IH, OFF_G2HH, OFF_GLU2, OFF_G3IH, OFF_G3HH,
                              OFF_GLU3, OFF_SKIP, OFF_SKIPG, OFF_SIG, OFF_GOUT};
__constant__ int T_OUT[15] = {192, 192, 480, 480, 160, 384, 384, 128, 384, 384, 128, 128, 128, 40, 4};
__constant__ int T_IN [15] = {328, 192, 272, 160, 160, 240, 128, 128, 208, 128, 128, 688, 128, 128, 192};

__global__ void k_transpose_all(WP wp) {
    int l = blockIdx.y;
    int i = blockIdx.x * blockDim.x + threadIdx.x;
    int out = T_OUT[l], in = T_IN[l];
    if (i < out * in) {
        int o = i / in, k = i - o * in;
        g_wt[T_OFF[l] + k * out + o] = wp.p[l][i];
    }
}

// ---------------- fd1: x = tanh([f, pembed] @ fd1_w^T) ----------------
__global__ void k_fd1(const float* __restrict__ feat, const int* __restrict__ period,
                      const float* __restrict__ pembed, const float* __restrict__ fd1) {
    int bt = blockIdx.x;                 // b*TF + t
    int b = bt / TF, t = bt - b * TF;
    __shared__ float xin[32];
    int tid = threadIdx.x;
    if (tid < 20) {
        xin[tid] = feat[(b * TT + (t + 2)) * 20 + tid];
    } else if (tid < 32) {
        int per = period[b * TT + t + 2];
        per = min(max(per, 32), 254);
        xin[tid] = pembed[(per - 32) * 12 + (tid - 20)];
    }
    __syncthreads();
    float acc = 0.0f;
    const float* w = fd1 + tid * 32;
#pragma unroll
    for (int k = 0; k < 32; k++) acc += w[k] * xin[k];
    g_x[(bt) * 64 + tid] = tanhf(acc);
}

// ---------------- fused conv1d + fd2 + gain ----------------
__global__ void k_front(const float* __restrict__ wconv, const float* __restrict__ fd2,
                        const float* __restrict__ cg_w, const float* __restrict__ cg_b) {
    int bt = blockIdx.x;                 // b*TC + t
    int b = bt / TC, t = bt - b * TC;
    __shared__ float xin[192];
    __shared__ float ybuf[128];
    __shared__ float condb[320];
    int tid = threadIdx.x;               // 320 threads
    for (int i = tid; i < 192; i += 320) {
        xin[i] = g_x[(b * TF + t + (i >> 6)) * 64 + (i & 63)];
    }
    __syncthreads();
    // conv: 128 out channels
    if (tid < 128) {
        float acc = 0.0f;
        const float* w = wconv + tid * 192;  // [oc][ic][kk]
#pragma unroll 8
        for (int ic = 0; ic < 64; ic++) {
            acc += w[ic * 3 + 0] * xin[0 * 64 + ic];
            acc += w[ic * 3 + 1] * xin[1 * 64 + ic];
            acc += w[ic * 3 + 2] * xin[2 * 64 + ic];
        }
        ybuf[tid] = tanhf(acc);
    }
    __syncthreads();
    // fd2: 320 outputs
    {
        float acc = 0.0f;
        const float* w = fd2 + tid * 128;
#pragma unroll 8
        for (int k = 0; k < 128; k++) acc += __ldg(w + k) * ybuf[k];
        float c = tanhf(acc);
        condb[tid] = c;
        g_cond[(size_t)bt * 320 + tid] = c;
    }
    __syncthreads();
    // gains for subs 0..3 of this frame
    if (tid < 4) {
        float acc = cg_b[0];
        const float* c = condb + tid * 80;
#pragma unroll 8
        for (int k = 0; k < 80; k++) acc += cg_w[k] * c[k];
        float g = 0.2f + 0.8f * sigf(acc);
        g = fminf(fmaxf(g, 0.001f), 20.0f);
        g_gain[(t * 4 + tid) * BATCH + b] = g;
    }
}

// ---------------- batched matvec: 4 batch elems (float4-packed), FFMA2 ----------------
// Wt is [IN][OUT]; x[k] = float4 of 4 batch values; y[o] = float4 outputs.
template <int IN, int OUT, int ACT>
__device__ __forceinline__ void matvec4(const float* __restrict__ Wt,
                                        const float4* __restrict__ x,
                                        float4* __restrict__ y,
                                        float4* __restrict__ red) {
    constexpr int RG = OUT / 4;                      // float4 weight row-groups
    constexpr int S0 = NT / RG;
    constexpr int S = (S0 > 32) ? 32 : S0;           // k-slices
    int tid = threadIdx.x;
    int sl = tid / RG;
    int rg = tid - sl * RG;
    if (sl < S) {
        u64 a01[4] = {0ull, 0ull, 0ull, 0ull};
        u64 a23[4] = {0ull, 0ull, 0ull, 0ull};
        const float4* __restrict__ W4 = reinterpret_cast<const float4*>(Wt) + rg;
#pragma unroll 8
        for (int k = sl; k < IN; k += S) {
            float4 xv = x[k];
            u64 x01 = pk2(xv.x, xv.y);
            u64 x23 = pk2(xv.z, xv.w);
            float4 w = __ldg(&W4[k * RG]);
            u64 w0 = dup2(w.x), w1 = dup2(w.y), w2 = dup2(w.z), w3 = dup2(w.w);
            fma2(a01[0], w0, x01); fma2(a23[0], w0, x23);
            fma2(a01[1], w1, x01); fma2(a23[1], w1, x23);
            fma2(a01[2], w2, x01); fma2(a23[2], w2, x23);
            fma2(a01[3], w3, x01); fma2(a23[3], w3, x23);
        }
        float4* r = red + sl * OUT + rg * 4;
#pragma unroll
        for (int o = 0; o < 4; o++) {
            float2 lo = upk(a01[o]), hi = upk(a23[o]);
            r[o] = make_float4(lo.x, lo.y, hi.x, hi.y);
        }
    }
    __syncthreads();
    for (int o = tid; o < OUT; o += NT) {
        float4 t = make_float4(0.f, 0.f, 0.f, 0.f);
#pragma unroll
        for (int ss = 0; ss < S; ss++) {
            float4 v = red[ss * OUT + o];
            t.x += v.x; t.y += v.y; t.z += v.z; t.w += v.w;
        }
        if (ACT == 1) t = tanh4v(t);
        y[o] = t;
    }
    __syncthreads();
}

// ---------------- GRU + GLU block (4-batch float4) ----------------
template <int H, int IN>
__device__ __forceinline__ void gru_glu4(const float* Wih, const float* Whh, const float* Wglu,
                                         const float4* x, float4* h, float4* g,
                                         float4* gi, float4* gh, float4* red) {
    matvec4<IN, 3 * H, 0>(Wih, x, gi, red);
    matvec4<H, 3 * H, 0>(Whh, h, gh, red);
    int tid = threadIdx.x;
    for (int o = tid; o < H; o += NT) {
        float4 ga = gi[o], gb = gh[o];
        float4 r = sig4v(make_float4(ga.x + gb.x, ga.y + gb.y, ga.z + gb.z, ga.w + gb.w));
        float4 gc = gi[H + o], gd = gh[H + o];
        float4 z = sig4v(make_float4(gc.x + gd.x, gc.y + gd.y, gc.z + gd.z, gc.w + gd.w));
        float4 ge = gi[2 * H + o], gf = gh[2 * H + o];
        float4 n = tanh4v(make_float4(ge.x + r.x * gf.x, ge.y + r.y * gf.y,
                                      ge.z + r.z * gf.z, ge.w + r.w * gf.w));
        float4 hv = h[o];
        hv.x = (1.0f - z.x) * n.x + z.x * hv.x;
        hv.y = (1.0f - z.y) * n.y + z.y * hv.y;
        hv.z = (1.0f - z.z) * n.z + z.z * hv.z;
        hv.w = (1.0f - z.w) * n.w + z.w * hv.w;
        h[o] = hv;
    }
    __syncthreads();
    matvec4<H, H, 0>(Wglu, h, gh, red);
    for (int o = tid; o < H; o += NT) {
        float4 u = sig4v(gh[o]);
        float4 hv = h[o];
        g[o] = make_float4(hv.x * u.x, hv.y * u.y, hv.z * u.z, hv.w * u.w);
    }
    __syncthreads();
}

// ---------------- dynamic-smem layout (floats/float4s) ----------------
#define N_RED    2048   // float4
#define N_F4     (N_RED + 328 + 160 + 128 + 128 + 192 + 192 + 480 + 480 + 160 + 128 + 128 + 688 + 128 + 4)
#define SMEM_BYTES (N_F4 * 16 + (4 * 256 + 4 + 4) * 4)

// ---------------- persistent scan: each CTA owns 4 batch chains ----------------
__global__ __launch_bounds__(NT, 1) void k_scan(const int* __restrict__ period,
                                                const float* __restrict__ gout_b,
                                                float* __restrict__ out) {
    int b0 = blockIdx.x * BPC;
    extern __shared__ float4 sm4[];
    float4* red4  = sm4;                 // 2048
    float4* xcat4 = red4 + N_RED;        // 328: [0:164) state, [164:328) tmp
    float4* s1_4  = xcat4 + 328;         // 160
    float4* s2_4  = s1_4 + 160;          // 128
    float4* s3_4  = s2_4 + 128;          // 128
    float4* bt4   = s3_4 + 128;          // 192 (tanh pre-glu)
    float4* fw4   = bt4 + 192;           // 192 (fwc_out)
    float4* gi4   = fw4 + 192;           // 480
    float4* gh4   = gi4 + 480;           // 480
    float4* g1_4  = gh4 + 480;           // 160
    float4* g2_4  = g1_4 + 160;          // 128
    float4* g3_4  = g2_4 + 128;          // 128
    float4* skin4 = g3_4 + 128;          // 688
    float4* skv4  = skin4 + 688;         // 128
    float4* pg4   = skv4 + 128;          // 4
    float*  excp  = (float*)(pg4 + 4);   // 4*256
    float*  sgain = excp + 4 * 256;      // 4
    int*    sper  = (int*)(sgain + 4);   // 4
    int tid = threadIdx.x;

    // init state to zero
    for (int i = tid; i < 4 * 256; i += NT) excp[i] = 0.0f;
    float4 z4 = make_float4(0.f, 0.f, 0.f, 0.f);
    for (int i = tid; i < 328; i += NT) xcat4[i] = z4;
    for (int i = tid; i < 160; i += NT) s1_4[i] = z4;
    for (int i = tid; i < 128; i += NT) s2_4[i] = z4;
    for (int i = tid; i < 128; i += NT) s3_4[i] = z4;
    __syncthreads();

    int base = 0;  // exc circular base
    for (int s = 0; s < NSTEP; s++) {
        int frame = s >> 2, sub = s & 3;
        // phase0: per-step scalars + shift state (tmp -> state)
        if (tid >= 504) {
            int u = tid - 504;
            if (u < 4) {
                int p = period[(b0 + u) * TT + 3 + frame];
                sper[u] = min(max(p, 32), 254);
            } else {
                sgain[u - 4] = g_gain[s * BATCH + b0 + (u - 4)];
            }
        }
        if (tid < 164) xcat4[tid] = xcat4[164 + tid];
        __syncthreads();
        // phase1: build tmp = [cond80 | pred44 | prev40] (batch-packed)
        if (tid < 164) {
            int j = tid;
            float4 v;
            if (j < 80) {
                size_t cb = (size_t)sub * 80 + j;
                v.x = g_cond[((size_t)((b0 + 0) * TC + frame)) * 320 + cb];
                v.y = g_cond[((size_t)((b0 + 1) * TC + frame)) * 320 + cb];
                v.z = g_cond[((size_t)((b0 + 2) * TC + frame)) * 320 + cb];
                v.w = g_cond[((size_t)((b0 + 3) * TC + frame)) * 320 + cb];
            } else if (j < 124) {
                int i2 = j - 80;
                float vv[4];
#pragma unroll
                for (int bb = 0; bb < 4; bb++) {
                    int idx = 254 - sper[bb] + i2;
                    if (idx >= 256) idx -= sper[bb];
                    idx = max(0, min(255, idx));
                    vv[bb] = excp[bb * 256 + ((base + idx) & 255)] / (1e-5f + sgain[bb]);
                }
                v = make_float4(vv[0], vv[1], vv[2], vv[3]);
            } else {
                int i2 = j - 124;
                float vv[4];
#pragma unroll
                for (int bb = 0; bb < 4; bb++) {
                    vv[bb] = excp[bb * 256 + ((base + 216 + i2) & 255)] / (1e-5f + sgain[bb]);
                }
                v = make_float4(vv[0], vv[1], vv[2], vv[3]);
            }
            xcat4[164 + j] = v;
        }
        __syncthreads();

        // fwc: t = tanh(fwc_w @ xcat); fwc_out = t * sig(fwc_glu @ t)
        matvec4<328, 192, 1>(g_wt + OFF_FWC, xcat4, bt4, red4);
        matvec4<192, 192, 0>(g_wt + OFF_FWCG, bt4, gh4, red4);
        for (int o = tid; o < 192; o += NT) {
            float4 u = sig4v(gh4[o]);
            float4 t = bt4[o];
            fw4[o] = make_float4(t.x * u.x, t.y * u.y, t.z * u.z, t.w * u.w);
        }
        __syncthreads();

        // pg = sigmoid(gout @ fwc_out + gout_b)
        matvec4<192, 4, 0>(g_wt + OFF_GOUT, fw4, pg4, red4);
        if (tid < 4) {
            float bsc = gout_b[tid];
            float4 p = pg4[tid];
            pg4[tid] = sig4v(make_float4(p.x + bsc, p.y + bsc, p.z + bsc, p.w + bsc));
        }
        __syncthreads();

        // fpitch = tmp[82:122] -> xcat4[164+82+i]; prev = xcat4[164+124+i]
        // GRU1 input (272): [fwc_out(192) | pg0*fpitch(40) | prev(40)]
        {
            float4 p0 = pg4[0];
            for (int j = tid; j < 272; j += NT) {
                float4 v;
                if (j < 192) v = fw4[j];
                else if (j < 232) {
                    float4 f = xcat4[164 + 82 + (j - 192)];
                    v = make_float4(p0.x * f.x, p0.y * f.y, p0.z * f.z, p0.w * f.w);
                } else v = xcat4[164 + 124 + (j - 232)];
                skin4[j] = v;
            }
        }
        __syncthreads();
        gru_glu4<160, 272>(g_wt + OFF_G1IH, g_wt + OFF_G1HH, g_wt + OFF_GLU1,
                           skin4, s1_4, g1_4, gi4, gh4, red4);

        // GRU2 input (240): [g1(160) | pg1*fpitch | prev]
        {
            float4 p1 = pg4[1];
            for (int j = tid; j < 240; j += NT) {
                float4 v;
                if (j < 160) v = g1_4[j];
                else if (j < 200) {
                    float4 f = xcat4[164 + 82 + (j - 160)];
                    v = make_float4(p1.x * f.x, p1.y * f.y, p1.z * f.z, p1.w * f.w);
                } else v = xcat4[164 + 124 + (j - 200)];
                skin4[j] = v;
            }
        }
        __syncthreads();
        gru_glu4<128, 240>(g_wt + OFF_G2IH, g_wt + OFF_G2HH, g_wt + OFF_GLU2,
                           skin4, s2_4, g2_4, gi4, gh4, red4);

        // GRU3 input (208): [g2(128) | pg2*fpitch | prev]
        {
            float4 p2 = pg4[2];
            for (int j = tid; j < 208; j += NT) {
                float4 v;
                if (j < 128) v = g2_4[j];
                else if (j < 168) {
                    float4 f = xcat4[164 + 82 + (j - 128)];
                    v = make_float4(p2.x * f.x, p2.y * f.y, p2.z * f.z, p2.w * f.w);
                } else v = xcat4[164 + 124 + (j - 168)];
                skin4[j] = v;
            }
        }
        __syncthreads();
        gru_glu4<128, 208>(g_wt + OFF_G3IH, g_wt + OFF_G3HH, g_wt + OFF_GLU3,
                           skin4, s3_4, g3_4, gi4, gh4, red4);

        // skip_in (688): [g1 | g2 | g3 | fwc_out | pg3*fpitch | prev]
        {
            float4 p3 = pg4[3];
            for (int j = tid; j < 688; j += NT) {
                float4 v;
                if (j < 160) v = g1_4[j];
                else if (j < 288) v = g2_4[j - 160];
                else if (j < 416) v = g3_4[j - 288];
                else if (j < 608) v = fw4[j - 416];
                else if (j < 648) {
                    float4 f = xcat4[164 + 82 + (j - 608)];
                    v = make_float4(p3.x * f.x, p3.y * f.y, p3.z * f.z, p3.w * f.w);
                } else v = xcat4[164 + 124 + (j - 648)];
                skin4[j] = v;
            }
        }
        __syncthreads();
        matvec4<688, 128, 1>(g_wt + OFF_SKIP, skin4, bt4, red4);
        matvec4<128, 128, 0>(g_wt + OFF_SKIPG, bt4, gh4, red4);
        for (int o = tid; o < 128; o += NT) {
            float4 u = sig4v(gh4[o]);
            float4 t = bt4[o];
            skv4[o] = make_float4(t.x * u.x, t.y * u.y, t.z * u.z, t.w * u.w);
        }
        __syncthreads();

        // sig = tanh(sig_w @ skip) * gain  -> output + exc push (gi4 as scratch)
        matvec4<128, 40, 1>(g_wt + OFF_SIG, skv4, gi4, red4);
        if (tid < 40) {
            float4 v = gi4[tid];
            v.x *= sgain[0]; v.y *= sgain[1]; v.z *= sgain[2]; v.w *= sgain[3];
            int pj = (base + tid) & 255;          // logical [216+tid] after base shift
            excp[0 * 256 + pj] = v.x;
            excp[1 * 256 + pj] = v.y;
            excp[2 * 256 + pj] = v.z;
            excp[3 * 256 + pj] = v.w;
            size_t ob = (size_t)b0 * 80000 + (size_t)s * 40 + tid;
            out[ob + 0 * 80000] = v.x;
            out[ob + 1 * 80000] = v.y;
            out[ob + 2 * 80000] = v.z;
            out[ob + 3 * 80000] = v.w;
        }
        __syncthreads();
        base = (base + 40) & 255;
    }
}

// ---------------- launch ----------------
extern "C" void kernel_launch(void* const* d_in, const int* in_sizes, int n_in,
                              void* d_out, int out_size) {
    const float* features = (const float*)d_in[0];
    const int*   period   = (const int*)d_in[1];
    const float* pembed   = (const float*)d_in[2];
    const float* fd1_w    = (const float*)d_in[3];
    const float* fconv1_w = (const float*)d_in[4];
    const float* fd2_w    = (const float*)d_in[5];
    const float* cg_w     = (const float*)d_in[6];
    const float* cg_b     = (const float*)d_in[7];
    const float* gout_b   = (const float*)d_in[23];
    float* out = (float*)d_out;

    WP wp;
    for (int i = 0; i < 15; i++) wp.p[i] = (const float*)d_in[8 + i];

    static int smem_set = 0;
    if (!smem_set) {
        cudaFuncSetAttribute(k_scan, cudaFuncAttributeMaxDynamicSharedMemorySize, SMEM_BYTES);
        smem_set = 1;
    }

    // 4 launches: transpose(1), fd1(2), front(3), scan(4)
    dim3 tg((130560 + 255) / 256, 15);   // max layer elems = 480*272
    k_transpose_all<<<tg, 256>>>(wp);
    k_fd1<<<BATCH * TF, 64>>>(features, period, pembed, fd1_w);
    k_front<<<BATCH * TC, 320>>>(fconv1_w, fd2_w, cg_w, cg_b);
    k_scan<<<NCTA, NT, SMEM_BYTES>>>(period, gout_b, out);
    (void)in_sizes; (void)n_in; (void)out_size;
}